// round 2
// baseline (speedup 1.0000x reference)
#include <cuda_runtime.h>
#include <cuda_bf16.h>
#include <math.h>
#include <stdint.h>

// Problem constants
#define NNODES 50000
#define NEDGES 800000
#define HID    128
#define EDIM   16
#define NLAYERS 3
#define NGRAPHS 256
#define BN_EPS 1e-5f

// ---------------- scratch (static device globals; no allocation) ----------------
__device__ float g_h[NNODES * HID];        // node hidden state
__device__ float g_t[NNODES * HID];        // t = h@W1h + b1; reused as agg
__device__ float g_s[NNODES * HID];        // scatter accumulator
__device__ float g_gi[NNODES * 3 * HID];   // GRU input gates
__device__ float g_gh[NNODES * 3 * HID];   // GRU hidden gates
__device__ float g_deg[NNODES];            // in-degree (float)
__device__ int   g_offs[NGRAPHS + 1];      // graph row offsets (batch is sorted)
__device__ float g_z[NGRAPHS * 2 * HID];   // [mean | max] readout features

// ---------------- generic K=128 fp32 GEMM: C[M,N] = A[M,128] @ B (+bias)(relu) --
// B layout: trans==0 -> B[k*ldb + n]; trans==1 -> B[n*ldb + k]
// epilogue: C = acc + bias[n] * (rowScale ? rowScale[m] : 1), optional relu
// Tiles: BM=128, BN=128, two K-chunks of 64. 256 threads, 8x8 microtile.
#define GEMM_SMEM ((128 * 64 + 64 * 132) * 4)

__global__ void __launch_bounds__(256, 2)
gemm_k128_kernel(const float* __restrict__ A, const float* __restrict__ B,
                 float* __restrict__ C, int M, int N, int ldb, int trans,
                 const float* __restrict__ bias, const float* __restrict__ rowScale,
                 int doRelu)
{
    extern __shared__ float smem[];
    float* As = smem;              // [128][64]
    float* Bs = smem + 128 * 64;   // [64][132] (pitch 132 keeps 16B alignment)

    const int m0 = blockIdx.x * 128;
    const int n0 = blockIdx.y * 128;
    const int tid = threadIdx.x;
    const int tx = tid & 15;       // n-direction
    const int ty = tid >> 4;       // m-direction

    float acc[64];
#pragma unroll
    for (int i = 0; i < 64; ++i) acc[i] = 0.f;

    for (int kc = 0; kc < 2; ++kc) {
        const int k0 = kc * 64;
        // --- load A tile [128m][64k], coalesced float4 ---
        {
            const int k4 = tid & 15;    // float4 index along k (16 per row)
            const int mr = tid >> 4;    // 16 rows per pass
#pragma unroll
            for (int p = 0; p < 8; ++p) {
                const int m = mr + p * 16;
                float4 v = make_float4(0.f, 0.f, 0.f, 0.f);
                const int gm = m0 + m;
                if (gm < M)
                    v = *(const float4*)(A + (size_t)gm * 128 + k0 + k4 * 4);
                *(float4*)(&As[m * 64 + k4 * 4]) = v;
            }
        }
        // --- load B tile into Bs[k][n] ---
        if (!trans) {
            const int n4 = tid & 31;    // 32 float4 per 128-wide row
            const int kr = tid >> 5;    // 8 rows per pass
#pragma unroll
            for (int p = 0; p < 8; ++p) {
                const int k = kr + p * 8;
                float4 v = *(const float4*)(B + (size_t)(k0 + k) * ldb + n0 + n4 * 4);
                *(float4*)(&Bs[k * 132 + n4 * 4]) = v;
            }
        } else {
            const int k4 = tid & 15;
            const int nr = tid >> 4;
#pragma unroll
            for (int p = 0; p < 8; ++p) {
                const int n = nr + p * 16;
                float4 v = *(const float4*)(B + (size_t)(n0 + n) * ldb + k0 + k4 * 4);
                Bs[(k4 * 4 + 0) * 132 + n] = v.x;
                Bs[(k4 * 4 + 1) * 132 + n] = v.y;
                Bs[(k4 * 4 + 2) * 132 + n] = v.z;
                Bs[(k4 * 4 + 3) * 132 + n] = v.w;
            }
        }
        __syncthreads();

#pragma unroll 8
        for (int k = 0; k < 64; ++k) {
            float a[8], b[8];
#pragma unroll
            for (int i = 0; i < 8; ++i) a[i] = As[(ty * 8 + i) * 64 + k];
            float4 b0 = *(const float4*)(&Bs[k * 132 + tx * 8]);
            float4 b1 = *(const float4*)(&Bs[k * 132 + tx * 8 + 4]);
            b[0] = b0.x; b[1] = b0.y; b[2] = b0.z; b[3] = b0.w;
            b[4] = b1.x; b[5] = b1.y; b[6] = b1.z; b[7] = b1.w;
#pragma unroll
            for (int i = 0; i < 8; ++i)
#pragma unroll
                for (int j = 0; j < 8; ++j)
                    acc[i * 8 + j] += a[i] * b[j];
        }
        __syncthreads();
    }

    // --- epilogue ---
    float4 bia0 = make_float4(0.f, 0.f, 0.f, 0.f);
    float4 bia1 = make_float4(0.f, 0.f, 0.f, 0.f);
    if (bias) {
        bia0 = *(const float4*)(bias + n0 + tx * 8);
        bia1 = *(const float4*)(bias + n0 + tx * 8 + 4);
    }
#pragma unroll
    for (int i = 0; i < 8; ++i) {
        const int m = m0 + ty * 8 + i;
        if (m >= M) continue;
        const float rs = rowScale ? rowScale[m] : 1.f;
        float4 o0, o1;
        o0.x = acc[i * 8 + 0] + bia0.x * rs;
        o0.y = acc[i * 8 + 1] + bia0.y * rs;
        o0.z = acc[i * 8 + 2] + bia0.z * rs;
        o0.w = acc[i * 8 + 3] + bia0.w * rs;
        o1.x = acc[i * 8 + 4] + bia1.x * rs;
        o1.y = acc[i * 8 + 5] + bia1.y * rs;
        o1.z = acc[i * 8 + 6] + bia1.z * rs;
        o1.w = acc[i * 8 + 7] + bia1.w * rs;
        if (doRelu) {
            o0.x = fmaxf(o0.x, 0.f); o0.y = fmaxf(o0.y, 0.f);
            o0.z = fmaxf(o0.z, 0.f); o0.w = fmaxf(o0.w, 0.f);
            o1.x = fmaxf(o1.x, 0.f); o1.y = fmaxf(o1.y, 0.f);
            o1.z = fmaxf(o1.z, 0.f); o1.w = fmaxf(o1.w, 0.f);
        }
        *(float4*)(C + (size_t)m * N + n0 + tx * 8)     = o0;
        *(float4*)(C + (size_t)m * N + n0 + tx * 8 + 4) = o1;
    }
}

// ---------------- per-edge: u = relu(t[src] + ea@W1e); s[dst] += u --------------
// warp per edge; W1e (16x128) held in registers (16 float4 per lane).
__global__ void __launch_bounds__(256)
edge_kernel(const int* __restrict__ ei, const float* __restrict__ ea,
            const float* __restrict__ t, float* __restrict__ s,
            const float* __restrict__ w1e)
{
    const int lane = threadIdx.x & 31;
    float4 w[16];
#pragma unroll
    for (int j = 0; j < 16; ++j)
        w[j] = *(const float4*)(w1e + j * 128 + lane * 4);

    const int warp = blockIdx.x * (blockDim.x >> 5) + (threadIdx.x >> 5);
    const int nw = gridDim.x * (blockDim.x >> 5);
    for (int e = warp; e < NEDGES; e += nw) {
        const int src = __ldg(ei + e);
        const int dst = __ldg(ei + NEDGES + e);
        float4 acc = *(const float4*)(t + (size_t)src * 128 + lane * 4);
        const float4* ev = (const float4*)(ea + (size_t)e * 16);
#pragma unroll
        for (int q = 0; q < 4; ++q) {
            const float4 e4 = __ldg(ev + q);
            const float4 w0 = w[q * 4 + 0], w1 = w[q * 4 + 1];
            const float4 w2 = w[q * 4 + 2], w3 = w[q * 4 + 3];
            acc.x += e4.x * w0.x + e4.y * w1.x + e4.z * w2.x + e4.w * w3.x;
            acc.y += e4.x * w0.y + e4.y * w1.y + e4.z * w2.y + e4.w * w3.y;
            acc.z += e4.x * w0.z + e4.y * w1.z + e4.z * w2.z + e4.w * w3.z;
            acc.w += e4.x * w0.w + e4.y * w1.w + e4.z * w2.w + e4.w * w3.w;
        }
        acc.x = fmaxf(acc.x, 0.f); acc.y = fmaxf(acc.y, 0.f);
        acc.z = fmaxf(acc.z, 0.f); acc.w = fmaxf(acc.w, 0.f);
        float* p = s + (size_t)dst * 128 + lane * 4;
        asm volatile("red.global.add.v4.f32 [%0], {%1,%2,%3,%4};"
                     :: "l"(p), "f"(acc.x), "f"(acc.y), "f"(acc.z), "f"(acc.w)
                     : "memory");
    }
}

// ---------------- degree count ----------------
__global__ void deg_kernel(const int* __restrict__ ei, float* __restrict__ deg)
{
    const int e = blockIdx.x * blockDim.x + threadIdx.x;
    if (e < NEDGES) atomicAdd(&deg[__ldg(ei + NEDGES + e)], 1.f);
}

// ---------------- fused GRU gates + BN + residual (in-place h update) -----------
__device__ __forceinline__ float gru1(float ir, float iz, float in_, float hr,
                                      float hz, float hn, float h,
                                      float ga, float be, float mu, float va)
{
    const float r = 1.f / (1.f + expf(-(ir + hr)));
    const float z = 1.f / (1.f + expf(-(iz + hz)));
    const float n = tanhf(in_ + r * hn);
    const float hnew = (1.f - z) * n + z * h;
    const float bn = (hnew - mu) * rsqrtf(va + BN_EPS) * ga + be;
    return h + bn;
}

__global__ void gru_bn_kernel(const float* __restrict__ gi, const float* __restrict__ gh,
                              float* __restrict__ h,
                              const float* __restrict__ gamma, const float* __restrict__ beta,
                              const float* __restrict__ mean,  const float* __restrict__ var)
{
    const int idx = blockIdx.x * blockDim.x + threadIdx.x; // one per float4 chunk
    if (idx >= NNODES * 32) return;
    const int m = idx >> 5;
    const int c = idx & 31;
    const size_t gb = (size_t)m * 384 + c * 4;
    const float4 ir = *(const float4*)(gi + gb);
    const float4 iz = *(const float4*)(gi + gb + 128);
    const float4 in_ = *(const float4*)(gi + gb + 256);
    const float4 hr = *(const float4*)(gh + gb);
    const float4 hz = *(const float4*)(gh + gb + 128);
    const float4 hn = *(const float4*)(gh + gb + 256);
    float4 hv = *(float4*)(h + (size_t)m * 128 + c * 4);
    const float4 ga = *(const float4*)(gamma + c * 4);
    const float4 be = *(const float4*)(beta + c * 4);
    const float4 mu = *(const float4*)(mean + c * 4);
    const float4 va = *(const float4*)(var + c * 4);
    hv.x = gru1(ir.x, iz.x, in_.x, hr.x, hz.x, hn.x, hv.x, ga.x, be.x, mu.x, va.x);
    hv.y = gru1(ir.y, iz.y, in_.y, hr.y, hz.y, hn.y, hv.y, ga.y, be.y, mu.y, va.y);
    hv.z = gru1(ir.z, iz.z, in_.z, hr.z, hz.z, hn.z, hv.z, ga.z, be.z, mu.z, va.z);
    hv.w = gru1(ir.w, iz.w, in_.w, hr.w, hz.w, hn.w, hv.w, ga.w, be.w, mu.w, va.w);
    *(float4*)(h + (size_t)m * 128 + c * 4) = hv;
}

// ---------------- graph offsets (batch is sorted) ----------------
__global__ void offsets_kernel(const int* __restrict__ batch, int* __restrict__ offs)
{
    const int g = blockIdx.x * blockDim.x + threadIdx.x;
    if (g > NGRAPHS) return;
    int lo = 0, hi = NNODES;
    while (lo < hi) {
        const int mid = (lo + hi) >> 1;
        if (batch[mid] < g) lo = mid + 1; else hi = mid;
    }
    offs[g] = lo;
}

// ---------------- segment mean+max readout ----------------
__global__ void readout_kernel(const float* __restrict__ h, const int* __restrict__ offs,
                               float* __restrict__ z)
{
    const int g = blockIdx.x;
    const int d = threadIdx.x;     // 128 threads
    const int s0 = offs[g], e0 = offs[g + 1];
    float sum = 0.f, mx = -INFINITY;
    for (int r = s0; r < e0; ++r) {
        const float v = h[(size_t)r * 128 + d];
        sum += v;
        mx = fmaxf(mx, v);
    }
    const int cnt = e0 - s0;
    float mean = sum / fmaxf((float)cnt, 1.f);
    if (cnt == 0) { mean = 0.f; mx = 0.f; }
    z[g * 256 + d] = mean;
    z[g * 256 + 128 + d] = mx;
}

// ---------------- final readout GEMM: out = relu(z @ ro_w + ro_b) ---------------
__global__ void ro_kernel(const float* __restrict__ z, const float* __restrict__ w,
                          const float* __restrict__ b, float* __restrict__ out)
{
    const int g = blockIdx.x;
    const int n = threadIdx.x;     // 128 threads
    __shared__ float zs[256];
    zs[n] = z[g * 256 + n];
    zs[n + 128] = z[g * 256 + 128 + n];
    __syncthreads();
    float acc = b[n];
#pragma unroll 8
    for (int k = 0; k < 256; ++k)
        acc += zs[k] * w[k * 128 + n];
    out[g * 128 + n] = fmaxf(acc, 0.f);
}

// ---------------- host orchestration ----------------
static void launch_gemm(const float* A, const float* B, float* C, int M, int N,
                        int ldb, int trans, const float* bias, const float* rowScale,
                        int relu)
{
    dim3 grid((M + 127) / 128, N / 128);
    gemm_k128_kernel<<<grid, 256, GEMM_SMEM>>>(A, B, C, M, N, ldb, trans, bias,
                                               rowScale, relu);
}

extern "C" void kernel_launch(void* const* d_in, const int* in_sizes, int n_in,
                              void* d_out, int out_size)
{
    const float* x     = (const float*)d_in[0];
    const int*   ei    = (const int*)d_in[1];
    const float* ea    = (const float*)d_in[2];
    const int*   batch = (const int*)d_in[3];
    const int base = (n_in >= 21) ? 5 : 4;  // skip scalar n_graphs if present
    const float* lin_w  = (const float*)d_in[base + 0];
    const float* lin_b  = (const float*)d_in[base + 1];
    const float* msg_w1 = (const float*)d_in[base + 2];  // [3,144,128]
    const float* msg_b1 = (const float*)d_in[base + 3];  // [3,128]
    const float* msg_w2 = (const float*)d_in[base + 4];  // [3,128,128]
    const float* msg_b2 = (const float*)d_in[base + 5];  // [3,128]
    const float* bn_g   = (const float*)d_in[base + 6];
    const float* bn_b   = (const float*)d_in[base + 7];
    const float* bn_m   = (const float*)d_in[base + 8];
    const float* bn_v   = (const float*)d_in[base + 9];
    const float* wih    = (const float*)d_in[base + 10]; // [3,384,128]
    const float* whh    = (const float*)d_in[base + 11]; // [3,384,128]
    const float* bih    = (const float*)d_in[base + 12]; // [3,384]
    const float* bhh    = (const float*)d_in[base + 13]; // [3,384]
    const float* ro_w   = (const float*)d_in[base + 14]; // [256,128]
    const float* ro_b   = (const float*)d_in[base + 15]; // [128]
    float* out = (float*)d_out;

    float *h, *t, *s, *gi, *gh, *deg, *z;
    int* offs;
    cudaGetSymbolAddress((void**)&h,   g_h);
    cudaGetSymbolAddress((void**)&t,   g_t);
    cudaGetSymbolAddress((void**)&s,   g_s);
    cudaGetSymbolAddress((void**)&gi,  g_gi);
    cudaGetSymbolAddress((void**)&gh,  g_gh);
    cudaGetSymbolAddress((void**)&deg, g_deg);
    cudaGetSymbolAddress((void**)&offs, g_offs);
    cudaGetSymbolAddress((void**)&z,   g_z);

    cudaFuncSetAttribute(gemm_k128_kernel,
                         cudaFuncAttributeMaxDynamicSharedMemorySize, GEMM_SMEM);

    // degree + graph offsets (once per launch)
    cudaMemsetAsync(deg, 0, NNODES * sizeof(float), 0);
    deg_kernel<<<(NEDGES + 255) / 256, 256>>>(ei, deg);
    offsets_kernel<<<2, 256>>>(batch, offs);

    // input projection: h = relu(x @ lin_w + lin_b)
    launch_gemm(x, lin_w, h, NNODES, HID, HID, 0, lin_b, nullptr, 1);

    for (int l = 0; l < NLAYERS; ++l) {
        const float* W1  = msg_w1 + (size_t)l * 144 * 128;   // [144,128]
        const float* W1e = W1 + 128 * 128;                   // rows 128..143
        const float* W2  = msg_w2 + (size_t)l * 128 * 128;

        // t = h @ W1h + b1
        launch_gemm(h, W1, t, NNODES, HID, 128, 0, msg_b1 + l * 128, nullptr, 0);
        // s = scatter_add(relu(t[src] + ea@W1e))
        cudaMemsetAsync(s, 0, (size_t)NNODES * HID * sizeof(float), 0);
        edge_kernel<<<1536, 256>>>(ei, ea, t, s, W1e);
        // agg = s @ W2 + deg*b2   (reuse t)
        launch_gemm(s, W2, t, NNODES, HID, 128, 0, msg_b2 + l * 128, deg, 0);
        // GRU input/hidden gate GEMMs
        launch_gemm(t, wih + (size_t)l * 384 * 128, gi, NNODES, 384, 128, 1,
                    bih + l * 384, nullptr, 0);
        launch_gemm(h, whh + (size_t)l * 384 * 128, gh, NNODES, 384, 128, 1,
                    bhh + l * 384, nullptr, 0);
        // gates + BN + residual, in-place h
        gru_bn_kernel<<<(NNODES * 32 + 255) / 256, 256>>>(
            gi, gh, h, bn_g + l * 128, bn_b + l * 128, bn_m + l * 128, bn_v + l * 128);
    }

    // readout
    readout_kernel<<<NGRAPHS, 128>>>(h, offs, z);
    ro_kernel<<<NGRAPHS, 128>>>(z, ro_w, ro_b, out);
}